// round 4
// baseline (speedup 1.0000x reference)
#include <cuda_runtime.h>
#include <cstdint>

#define B_  2
#define S_  2048
#define D_  1024
#define H_  16
#define DK_ 64

typedef unsigned int u32;

// ---------------- scratch (device globals: allocation-free) ----------------
__device__ float g_Qp[(size_t)B_ * S_ * D_];               // 16 MB
__device__ float g_Kp[(size_t)B_ * S_ * D_];
__device__ float g_Vp[(size_t)B_ * S_ * D_];
__device__ float g_Oh[(size_t)B_ * S_ * D_];
__device__ float g_S1[(size_t)B_ * H_ * S_ * S_];          // 512 MB
__device__ float g_S2[(size_t)B_ * H_ * S_ * S_];          // 512 MB

// ---------------- helpers ----------------
__device__ __forceinline__ u32 f2t(float x) {
    u32 r;
    asm("cvt.rna.tf32.f32 %0, %1;" : "=r"(r) : "f"(x));
    return r;
}

__device__ __forceinline__ void mma8(float* c, const u32* a, const u32* b) {
    asm volatile(
        "mma.sync.aligned.m16n8k8.row.col.f32.tf32.tf32.f32 "
        "{%0,%1,%2,%3},{%4,%5,%6,%7},{%8,%9},{%0,%1,%2,%3};\n"
        : "+f"(c[0]), "+f"(c[1]), "+f"(c[2]), "+f"(c[3])
        : "r"(a[0]), "r"(a[1]), "r"(a[2]), "r"(a[3]), "r"(b[0]), "r"(b[1]));
}

struct GP {
    const float* A;
    const float* B;
    float*       C;
    const float* bias;   // EPI==1
    const int*   mask;   // EPI==2
    long lda, ldb, ldc;
    long Ab, Ah, Bb, Bh, Cb, Ch, maskB;
    float scale;
    int M, N, K;
};

// ---------------- generic tf32 tensor-core GEMM ----------------
// BT: B operand is [N,K] row-major (NT GEMM). Otherwise B is [K,N] row-major (NN).
// EPI: 0 plain store, 1 +bias[n], 2 mask(q,n) ? v*scale : 0
template<int BM, int BN, int BK, int WMN, int WNN, bool BT, int EPI>
__global__ __launch_bounds__(256) void gemm_k(GP p) {
    static_assert(WMN * WNN == 8, "8 warps");
    constexpr int WTM  = BM / WMN;
    constexpr int WTN  = BN / WNN;
    constexpr int MT   = WTM / 16;
    constexpr int NT   = WTN / 8;
    constexpr int LDAS = BK + 4;
    constexpr int LDBS = BT ? (BK + 4) : (BN + 8);
    constexpr int BSZ  = BT ? BN * LDBS : BK * LDBS;
    constexpr int AF4  = BM * BK / 1024;   // float4 copies per thread
    constexpr int BF4  = BN * BK / 1024;
    constexpr int NQ4  = BN / 4;

    __shared__ u32 As[BM * LDAS];
    __shared__ u32 Bs[BSZ];

    const int tid  = threadIdx.x;
    const int wid  = tid >> 5, lane = tid & 31;
    const int wm   = wid / WNN, wn = wid % WNN;
    const int g    = lane >> 2, tg = lane & 3;
    const int z    = blockIdx.z;
    const int b    = z / H_, h = z % H_;

    const float* A  = p.A + (long)b * p.Ab + (long)h * p.Ah
                          + (long)blockIdx.y * BM * p.lda;
    const float* Bg = p.B + (long)b * p.Bb + (long)h * p.Bh
                          + (BT ? (long)blockIdx.x * BN * p.ldb
                                : (long)blockIdx.x * BN);

    float4 aR[AF4], bR[BF4];

    auto ldA = [&](int kt) {
#pragma unroll
        for (int i = 0; i < AF4; i++) {
            int fid = tid + i * 256;
            int r = fid >> 3, kq = (fid & 7) << 2;
            aR[i] = *(const float4*)(A + (long)r * p.lda + (long)kt * BK + kq);
        }
    };
    auto ldB = [&](int kt) {
#pragma unroll
        for (int i = 0; i < BF4; i++) {
            int fid = tid + i * 256;
            if constexpr (BT) {
                int n = fid >> 3, kq = (fid & 7) << 2;
                bR[i] = *(const float4*)(Bg + (long)n * p.ldb + (long)kt * BK + kq);
            } else {
                int k = fid / NQ4, nq = (fid % NQ4) << 2;
                bR[i] = *(const float4*)(Bg + (long)(kt * BK + k) * p.ldb + nq);
            }
        }
    };
    auto stA = [&]() {
#pragma unroll
        for (int i = 0; i < AF4; i++) {
            int fid = tid + i * 256;
            int r = fid >> 3, kq = (fid & 7) << 2;
            uint4 v = make_uint4(f2t(aR[i].x), f2t(aR[i].y), f2t(aR[i].z), f2t(aR[i].w));
            *(uint4*)&As[r * LDAS + kq] = v;
        }
    };
    auto stB = [&]() {
#pragma unroll
        for (int i = 0; i < BF4; i++) {
            int fid = tid + i * 256;
            uint4 v = make_uint4(f2t(bR[i].x), f2t(bR[i].y), f2t(bR[i].z), f2t(bR[i].w));
            if constexpr (BT) {
                int n = fid >> 3, kq = (fid & 7) << 2;
                *(uint4*)&Bs[n * LDBS + kq] = v;
            } else {
                int k = fid / NQ4, nq = (fid % NQ4) << 2;
                *(uint4*)&Bs[k * LDBS + nq] = v;
            }
        }
    };

    float acc[MT][NT][4];
#pragma unroll
    for (int i = 0; i < MT; i++)
#pragma unroll
        for (int j = 0; j < NT; j++)
#pragma unroll
            for (int k = 0; k < 4; k++) acc[i][j][k] = 0.f;

    const int KT = p.K / BK;
    ldA(0); ldB(0);
    stA(); stB();
    __syncthreads();

    for (int kt = 0; kt < KT; kt++) {
        if (kt + 1 < KT) { ldA(kt + 1); ldB(kt + 1); }
#pragma unroll
        for (int ks = 0; ks < BK / 8; ks++) {
            u32 af[MT][4], bf[NT][2];
            const int kk = ks * 8 + tg;
#pragma unroll
            for (int i = 0; i < MT; i++) {
                int r = wm * WTM + i * 16 + g;
                af[i][0] = As[r * LDAS + kk];
                af[i][1] = As[(r + 8) * LDAS + kk];
                af[i][2] = As[r * LDAS + kk + 4];
                af[i][3] = As[(r + 8) * LDAS + kk + 4];
            }
#pragma unroll
            for (int j = 0; j < NT; j++) {
                int c = wn * WTN + j * 8 + g;
                if constexpr (BT) {
                    bf[j][0] = Bs[c * LDBS + kk];
                    bf[j][1] = Bs[c * LDBS + kk + 4];
                } else {
                    bf[j][0] = Bs[kk * LDBS + c];
                    bf[j][1] = Bs[(kk + 4) * LDBS + c];
                }
            }
#pragma unroll
            for (int i = 0; i < MT; i++)
#pragma unroll
                for (int j = 0; j < NT; j++)
                    mma8(acc[i][j], af[i], bf[j]);
        }
        __syncthreads();
        if (kt + 1 < KT) { stA(); stB(); __syncthreads(); }
    }

    // ---------------- epilogue ----------------
    float* C = p.C + (long)b * p.Cb + (long)h * p.Ch;
    const long row0 = (long)blockIdx.y * BM + wm * WTM;
    const long col0 = (long)blockIdx.x * BN + wn * WTN;

#pragma unroll
    for (int i = 0; i < MT; i++) {
        const long r0 = row0 + i * 16 + g;
#pragma unroll
        for (int j = 0; j < NT; j++) {
            const long c = col0 + j * 8 + tg * 2;
            float v0 = acc[i][j][0], v1 = acc[i][j][1];
            float v2 = acc[i][j][2], v3 = acc[i][j][3];
            if constexpr (EPI == 1) {
                float b0 = p.bias[c], b1 = p.bias[c + 1];
                v0 += b0; v1 += b1; v2 += b0; v3 += b1;
            }
            if constexpr (EPI == 2) {
                const int* mb = p.mask + (long)b * p.maskB;
                v0 = mb[r0 * p.N + c]       ? v0 * p.scale : 0.f;
                v1 = mb[r0 * p.N + c + 1]   ? v1 * p.scale : 0.f;
                v2 = mb[(r0 + 8) * p.N + c]     ? v2 * p.scale : 0.f;
                v3 = mb[(r0 + 8) * p.N + c + 1] ? v3 * p.scale : 0.f;
            }
            *(float2*)(C + r0 * p.ldc + c)       = make_float2(v0, v1);
            *(float2*)(C + (r0 + 8) * p.ldc + c) = make_float2(v2, v3);
        }
    }
}

// ---------------- masked softmax with nan_to_num (one block per row) ----------------
__global__ __launch_bounds__(256) void softmax_k(float* __restrict__ S,
                                                 const int* __restrict__ mask) {
    const long r  = blockIdx.x;                 // [0, B*H*S)
    const int  q  = (int)(r & (S_ - 1));
    const int  bh = (int)(r >> 11);             // S_=2048
    const int  b  = bh >> 4;                    // /H_
    float* row = S + r * (long)S_;
    const int* mrow = mask + ((long)b * S_ + q) * (long)S_;
    const int tid = threadIdx.x;

    float4 x0 = ((const float4*)row)[tid];
    float4 x1 = ((const float4*)row)[tid + 256];
    int4   m0 = ((const int4*)mrow)[tid];
    int4   m1 = ((const int4*)mrow)[tid + 256];
    float xs[8] = {x0.x, x0.y, x0.z, x0.w, x1.x, x1.y, x1.z, x1.w};
    int   ms[8] = {m0.x, m0.y, m0.z, m0.w, m1.x, m1.y, m1.z, m1.w};

    float lmax = -3.402823466e38f;
#pragma unroll
    for (int i = 0; i < 8; i++)
        if (ms[i]) lmax = fmaxf(lmax, xs[i]);
#pragma unroll
    for (int o = 16; o > 0; o >>= 1)
        lmax = fmaxf(lmax, __shfl_xor_sync(0xffffffffu, lmax, o));

    __shared__ float sm[8];
    if ((tid & 31) == 0) sm[tid >> 5] = lmax;
    __syncthreads();
    float bmax = sm[0];
#pragma unroll
    for (int i = 1; i < 8; i++) bmax = fmaxf(bmax, sm[i]);
    __syncthreads();

    float es[8];
    float lsum = 0.f;
#pragma unroll
    for (int i = 0; i < 8; i++) {
        es[i] = ms[i] ? expf(xs[i] - bmax) : 0.f;
        lsum += es[i];
    }
#pragma unroll
    for (int o = 16; o > 0; o >>= 1)
        lsum += __shfl_xor_sync(0xffffffffu, lsum, o);
    if ((tid & 31) == 0) sm[tid >> 5] = lsum;
    __syncthreads();
    float bsum = 0.f;
#pragma unroll
    for (int i = 0; i < 8; i++) bsum += sm[i];

    const float inv = (bsum > 0.f) ? 1.f / bsum : 0.f;   // all-masked row -> zeros
    x0 = make_float4(es[0] * inv, es[1] * inv, es[2] * inv, es[3] * inv);
    x1 = make_float4(es[4] * inv, es[5] * inv, es[6] * inv, es[7] * inv);
    ((float4*)row)[tid]       = x0;
    ((float4*)row)[tid + 256] = x1;
}

// ---------------- launch ----------------
extern "C" void kernel_launch(void* const* d_in, const int* in_sizes, int n_in,
                              void* d_out, int out_size) {
    (void)in_sizes; (void)n_in; (void)out_size;
    const float* inq  = (const float*)d_in[0];
    const float* ink  = (const float*)d_in[1];
    const float* invv = (const float*)d_in[2];
    const int*   mask = (const int*)d_in[3];
    const float* prop = (const float*)d_in[4];
    const float* Wq = (const float*)d_in[5];
    const float* bq = (const float*)d_in[6];
    const float* Wk = (const float*)d_in[7];
    const float* bk = (const float*)d_in[8];
    const float* Wv = (const float*)d_in[9];
    const float* bv = (const float*)d_in[10];
    const float* Wo = (const float*)d_in[11];
    const float* bo = (const float*)d_in[12];

    float *Qp, *Kp, *Vp, *Oh, *S1, *S2;
    cudaGetSymbolAddress((void**)&Qp, g_Qp);
    cudaGetSymbolAddress((void**)&Kp, g_Kp);
    cudaGetSymbolAddress((void**)&Vp, g_Vp);
    cudaGetSymbolAddress((void**)&Oh, g_Oh);
    cudaGetSymbolAddress((void**)&S1, g_S1);
    cudaGetSymbolAddress((void**)&S2, g_S2);

    dim3 blk(256);

    // 1-3: projections  C[4096,1024] = X @ W + b
    {
        GP p{};
        p.lda = D_; p.ldb = D_; p.ldc = D_;
        p.M = B_ * S_; p.N = D_; p.K = D_;
        dim3 grid(D_ / 128, (B_ * S_) / 128, 1);
        p.A = inq;  p.B = Wq; p.bias = bq; p.C = Qp;
        gemm_k<128, 128, 32, 2, 4, false, 1><<<grid, blk>>>(p);
        p.A = ink;  p.B = Wk; p.bias = bk; p.C = Kp;
        gemm_k<128, 128, 32, 2, 4, false, 1><<<grid, blk>>>(p);
        p.A = invv; p.B = Wv; p.bias = bv; p.C = Vp;
        gemm_k<128, 128, 32, 2, 4, false, 1><<<grid, blk>>>(p);
    }

    // 4: S1[b,h,q,k] = mask ? (Q.K^T)/8 : 0   (batched NT, fused mask epilogue)
    {
        GP p{};
        p.A = Qp; p.lda = D_; p.Ab = (long)S_ * D_; p.Ah = DK_;
        p.B = Kp; p.ldb = D_; p.Bb = (long)S_ * D_; p.Bh = DK_;
        p.C = S1; p.ldc = S_; p.Cb = (long)H_ * S_ * S_; p.Ch = (long)S_ * S_;
        p.mask = mask; p.maskB = (long)S_ * S_;
        p.scale = 0.125f;
        p.M = S_; p.N = S_; p.K = DK_;
        dim3 grid(S_ / 128, S_ / 128, B_ * H_);
        gemm_k<128, 128, 32, 2, 4, true, 2><<<grid, blk>>>(p);
    }

    // 5: S2 = S1 @ P^T   (batched NT, the dominant 550 GFLOP GEMM)
    {
        GP p{};
        p.A = S1; p.lda = S_; p.Ab = (long)H_ * S_ * S_; p.Ah = (long)S_ * S_;
        p.B = prop; p.ldb = S_;
        p.C = S2; p.ldc = S_; p.Cb = (long)H_ * S_ * S_; p.Ch = (long)S_ * S_;
        p.M = S_; p.N = S_; p.K = S_;
        dim3 grid(S_ / 128, S_ / 128, B_ * H_);
        gemm_k<128, 128, 32, 2, 4, true, 0><<<grid, blk>>>(p);
    }

    // 6: masked softmax + nan_to_num, in place on S2
    softmax_k<<<B_ * H_ * S_, 256>>>(S2, mask);

    // 7: Oh[b,q,h*64+d] = softmax(S2) @ V   (batched NN, N=64)
    {
        GP p{};
        p.A = S2; p.lda = S_; p.Ab = (long)H_ * S_ * S_; p.Ah = (long)S_ * S_;
        p.B = Vp; p.ldb = D_; p.Bb = (long)S_ * D_; p.Bh = DK_;
        p.C = Oh; p.ldc = D_; p.Cb = (long)S_ * D_; p.Ch = DK_;
        p.M = S_; p.N = DK_; p.K = S_;
        dim3 grid(1, S_ / 128, B_ * H_);
        gemm_k<128, 64, 32, 4, 2, false, 0><<<grid, blk>>>(p);
    }

    // 8: out = Oh @ Wo + bo
    {
        GP p{};
        p.A = Oh; p.lda = D_;
        p.B = Wo; p.ldb = D_;
        p.bias = bo;
        p.C = (float*)d_out; p.ldc = D_;
        p.M = B_ * S_; p.N = D_; p.K = D_;
        dim3 grid(D_ / 128, (B_ * S_) / 128, 1);
        gemm_k<128, 128, 32, 2, 4, false, 1><<<grid, blk>>>(p);
    }
}

// round 6
// speedup vs baseline: 1.9234x; 1.9234x over previous
#include <cuda_runtime.h>
#include <cuda_fp16.h>
#include <cstdint>

#define B_  2
#define S_  2048
#define D_  1024
#define H_  16
#define DK_ 64

typedef unsigned int u32;

// ---------------- scratch (device globals: allocation-free) ----------------
__device__ __half g_Xq[(size_t)B_ * S_ * D_];      // fp16 inputs (8 MB each)
__device__ __half g_Xk[(size_t)B_ * S_ * D_];
__device__ __half g_Xv[(size_t)B_ * S_ * D_];
__device__ __half g_Qh[(size_t)B_ * S_ * D_];      // projected Q/K
__device__ __half g_Kh[(size_t)B_ * S_ * D_];
__device__ __half g_Vt[(size_t)B_ * S_ * D_];      // V transposed [b][h][dk][S]
__device__ __half g_Oh[(size_t)B_ * S_ * D_];      // attention output (pre Wo)
__device__ __half g_Ph[(size_t)S_ * S_];           // fp16 propagation matrix
__device__ __half g_Wqt[(size_t)D_ * D_];          // transposed fp16 weights [N][K]
__device__ __half g_Wkt[(size_t)D_ * D_];
__device__ __half g_Wvt[(size_t)D_ * D_];
__device__ __half g_Wot[(size_t)D_ * D_];
__device__ __half g_S1[(size_t)B_ * H_ * S_ * S_]; // 256 MB
__device__ __half g_S2[(size_t)B_ * H_ * S_ * S_]; // 256 MB

// ---------------- fp16 mma ----------------
__device__ __forceinline__ void mma16(float* c, const u32* a, const u32* b) {
    asm volatile(
        "mma.sync.aligned.m16n8k16.row.col.f32.f16.f16.f32 "
        "{%0,%1,%2,%3},{%4,%5,%6,%7},{%8,%9},{%0,%1,%2,%3};\n"
        : "+f"(c[0]), "+f"(c[1]), "+f"(c[2]), "+f"(c[3])
        : "r"(a[0]), "r"(a[1]), "r"(a[2]), "r"(a[3]), "r"(b[0]), "r"(b[1]));
}

struct HP {
    const __half* A;
    const __half* Bm;
    void*         C;
    const float*  bias;   // EPI 1/3/4
    const int*    mask;   // EPI 2
    long lda, ldb, ldc;
    long Ab, Ah, Bb, Bh, Cb, Ch, maskB;
    float scale;
    int  K;
};

// ---------------- generic fp16 NT tensor-core GEMM ----------------
// C[m][n] = sum_k A[m][k] * B[n][k]   (both K-contiguous fp16)
// EPI: 0 plain fp16, 1 +bias fp16, 2 mask?v*scale:0 fp16,
//      3 +bias then V-transposed fp16 store, 4 +bias fp32 store
template<int BM, int BN, int BK, int WMN, int WNN, int EPI>
__global__ __launch_bounds__(256) void gemm_h(HP p) {
    static_assert(WMN * WNN == 8, "8 warps");
    constexpr int WTM = BM / WMN;
    constexpr int WTN = BN / WNN;
    constexpr int MT  = WTM / 16;
    constexpr int NTj = WTN / 8;
    constexpr int LD  = BK + 8;               // halves
    constexpr int AF  = BM * BK / (8 * 256);  // uint4 (8 half) copies / thread
    constexpr int BF  = BN * BK / (8 * 256);
    constexpr int RQ  = BK / 8;               // uint4 per row

    __shared__ __half As[BM * LD];
    __shared__ __half Bs[BN * LD];

    const int tid  = threadIdx.x;
    const int wid  = tid >> 5, lane = tid & 31;
    const int wm   = wid / WNN, wn = wid % WNN;
    const int g    = lane >> 2, tg = lane & 3;
    const int z    = blockIdx.z;
    const int b    = z / H_, h = z % H_;

    const __half* Ab = p.A + (long)b * p.Ab + (long)h * p.Ah
                           + (long)blockIdx.y * BM * p.lda;
    const __half* Bb = p.Bm + (long)b * p.Bb + (long)h * p.Bh
                            + (long)blockIdx.x * BN * p.ldb;

    uint4 aR[AF], bR[BF];

    auto ldA = [&](int kt) {
#pragma unroll
        for (int i = 0; i < AF; i++) {
            int fid = tid + i * 256;
            int r = fid / RQ, kq = (fid % RQ) * 8;
            aR[i] = *(const uint4*)(Ab + (long)r * p.lda + kt * BK + kq);
        }
    };
    auto ldB = [&](int kt) {
#pragma unroll
        for (int i = 0; i < BF; i++) {
            int fid = tid + i * 256;
            int r = fid / RQ, kq = (fid % RQ) * 8;
            bR[i] = *(const uint4*)(Bb + (long)r * p.ldb + kt * BK + kq);
        }
    };
    auto stA = [&]() {
#pragma unroll
        for (int i = 0; i < AF; i++) {
            int fid = tid + i * 256;
            int r = fid / RQ, kq = (fid % RQ) * 8;
            *(uint4*)&As[r * LD + kq] = aR[i];
        }
    };
    auto stB = [&]() {
#pragma unroll
        for (int i = 0; i < BF; i++) {
            int fid = tid + i * 256;
            int r = fid / RQ, kq = (fid % RQ) * 8;
            *(uint4*)&Bs[r * LD + kq] = bR[i];
        }
    };

    float acc[MT][NTj][4];
#pragma unroll
    for (int i = 0; i < MT; i++)
#pragma unroll
        for (int j = 0; j < NTj; j++)
#pragma unroll
            for (int k = 0; k < 4; k++) acc[i][j][k] = 0.f;

    const int KT = p.K / BK;
    ldA(0); ldB(0);
    stA(); stB();
    __syncthreads();

    for (int kt = 0; kt < KT; kt++) {
        if (kt + 1 < KT) { ldA(kt + 1); ldB(kt + 1); }
#pragma unroll
        for (int ks = 0; ks < BK / 16; ks++) {
            u32 af[MT][4], bf[NTj][2];
            const int kk = ks * 16 + tg * 2;
#pragma unroll
            for (int i = 0; i < MT; i++) {
                int r = wm * WTM + i * 16 + g;
                af[i][0] = *(const u32*)&As[r * LD + kk];
                af[i][1] = *(const u32*)&As[(r + 8) * LD + kk];
                af[i][2] = *(const u32*)&As[r * LD + kk + 8];
                af[i][3] = *(const u32*)&As[(r + 8) * LD + kk + 8];
            }
#pragma unroll
            for (int j = 0; j < NTj; j++) {
                int c = wn * WTN + j * 8 + g;
                bf[j][0] = *(const u32*)&Bs[c * LD + kk];
                bf[j][1] = *(const u32*)&Bs[c * LD + kk + 8];
            }
#pragma unroll
            for (int i = 0; i < MT; i++)
#pragma unroll
                for (int j = 0; j < NTj; j++)
                    mma16(acc[i][j], af[i], bf[j]);
        }
        __syncthreads();
        if (kt + 1 < KT) { stA(); stB(); __syncthreads(); }
    }

    // ---------------- epilogue ----------------
    const long row0 = (long)blockIdx.y * BM + wm * WTM;
    const long col0 = (long)blockIdx.x * BN + wn * WTN;

#pragma unroll
    for (int i = 0; i < MT; i++) {
        const long r0 = row0 + i * 16 + g;
#pragma unroll
        for (int j = 0; j < NTj; j++) {
            const long c = col0 + j * 8 + tg * 2;
            float v0 = acc[i][j][0], v1 = acc[i][j][1];
            float v2 = acc[i][j][2], v3 = acc[i][j][3];
            if constexpr (EPI == 1 || EPI == 3 || EPI == 4) {
                float b0 = p.bias[c], b1 = p.bias[c + 1];
                v0 += b0; v1 += b1; v2 += b0; v3 += b1;
            }
            if constexpr (EPI == 2) {
                const int* mb = p.mask + (long)b * p.maskB;
                v0 = mb[r0 * S_ + c]           ? v0 * p.scale : 0.f;
                v1 = mb[r0 * S_ + c + 1]       ? v1 * p.scale : 0.f;
                v2 = mb[(r0 + 8) * S_ + c]     ? v2 * p.scale : 0.f;
                v3 = mb[(r0 + 8) * S_ + c + 1] ? v3 * p.scale : 0.f;
            }
            if constexpr (EPI == 3) {
                // Vt[((b*H + h)*64 + d)*S + s] : rows r0 span both batches
                __half* Ct = (__half*)p.C;
                const int hh = (int)(c >> 6), d = (int)(c & 63);
                {
                    const long bb = r0 >> 11, s = r0 & (S_ - 1);
                    __half* base = Ct + ((bb * H_ + hh) * 64 + d) * (long)S_ + s;
                    base[0]  = __float2half_rn(v0);
                    base[S_] = __float2half_rn(v1);
                }
                {
                    const long bb = (r0 + 8) >> 11, s = (r0 + 8) & (S_ - 1);
                    __half* base = Ct + ((bb * H_ + hh) * 64 + d) * (long)S_ + s;
                    base[0]  = __float2half_rn(v2);
                    base[S_] = __float2half_rn(v3);
                }
            } else if constexpr (EPI == 4) {
                float* C = (float*)p.C + (long)b * p.Cb + (long)h * p.Ch;
                *(float2*)(C + r0 * p.ldc + c)       = make_float2(v0, v1);
                *(float2*)(C + (r0 + 8) * p.ldc + c) = make_float2(v2, v3);
            } else {
                __half* C = (__half*)p.C + (long)b * p.Cb + (long)h * p.Ch;
                *(__half2*)(C + r0 * p.ldc + c)       = __floats2half2_rn(v0, v1);
                *(__half2*)(C + (r0 + 8) * p.ldc + c) = __floats2half2_rn(v2, v3);
            }
        }
    }
}

// ---------------- fp32 -> fp16 copy (4 elements / thread) ----------------
__global__ __launch_bounds__(256) void cvt_k(const float4* __restrict__ in,
                                             uint2* __restrict__ out) {
    long i = (long)blockIdx.x * 256 + threadIdx.x;
    float4 v = in[i];
    __half2 lo = __floats2half2_rn(v.x, v.y);
    __half2 hi = __floats2half2_rn(v.z, v.w);
    out[i] = make_uint2(*(u32*)&lo, *(u32*)&hi);
}

// ---------------- fp32 [K][N] -> fp16 [N][K] transpose (1024x1024) -----------
__global__ __launch_bounds__(256) void tr_k(const float* __restrict__ in,
                                            __half* __restrict__ out) {
    __shared__ float t[32][33];
    const int bx = blockIdx.x * 32, by = blockIdx.y * 32;
    const int x = threadIdx.x, y0 = threadIdx.y * 4;
#pragma unroll
    for (int i = 0; i < 4; i++)
        t[y0 + i][x] = in[(long)(by + y0 + i) * D_ + bx + x];
    __syncthreads();
#pragma unroll
    for (int i = 0; i < 4; i++)
        out[(long)(bx + y0 + i) * D_ + by + x] = __float2half_rn(t[x][y0 + i]);
}

// ---------------- masked softmax + nan_to_num, fp16 in-place ----------------
__global__ __launch_bounds__(256) void softmax_h(__half* __restrict__ S,
                                                 const int* __restrict__ mask) {
    const long r  = blockIdx.x;                 // [0, B*H*S)
    const int  q  = (int)(r & (S_ - 1));
    const int  bh = (int)(r >> 11);
    const int  b  = bh >> 4;
    __half* row = S + r * (long)S_;
    const int* mrow = mask + ((long)b * S_ + q) * (long)S_;
    const int tid = threadIdx.x;

    uint4 xr = ((const uint4*)row)[tid];        // 8 halves
    int4  m0 = ((const int4*)mrow)[2 * tid];
    int4  m1 = ((const int4*)mrow)[2 * tid + 1];
    const __half2* hp = (const __half2*)&xr;
    float xs[8];
#pragma unroll
    for (int i = 0; i < 4; i++) {
        float2 f = __half22float2(hp[i]);
        xs[i * 2] = f.x; xs[i * 2 + 1] = f.y;
    }
    int ms[8] = {m0.x, m0.y, m0.z, m0.w, m1.x, m1.y, m1.z, m1.w};

    float lmax = -3.402823466e38f;
#pragma unroll
    for (int i = 0; i < 8; i++)
        if (ms[i]) lmax = fmaxf(lmax, xs[i]);
#pragma unroll
    for (int o = 16; o > 0; o >>= 1)
        lmax = fmaxf(lmax, __shfl_xor_sync(0xffffffffu, lmax, o));

    __shared__ float sm[8];
    if ((tid & 31) == 0) sm[tid >> 5] = lmax;
    __syncthreads();
    float bmax = sm[0];
#pragma unroll
    for (int i = 1; i < 8; i++) bmax = fmaxf(bmax, sm[i]);
    __syncthreads();

    float es[8];
    float lsum = 0.f;
#pragma unroll
    for (int i = 0; i < 8; i++) {
        es[i] = ms[i] ? expf(xs[i] - bmax) : 0.f;
        lsum += es[i];
    }
#pragma unroll
    for (int o = 16; o > 0; o >>= 1)
        lsum += __shfl_xor_sync(0xffffffffu, lsum, o);
    if ((tid & 31) == 0) sm[tid >> 5] = lsum;
    __syncthreads();
    float bsum = 0.f;
#pragma unroll
    for (int i = 0; i < 8; i++) bsum += sm[i];

    const float inv = (bsum > 0.f) ? 1.f / bsum : 0.f;
    uint4 outr;
    __half2* op = (__half2*)&outr;
#pragma unroll
    for (int i = 0; i < 4; i++)
        op[i] = __floats2half2_rn(es[i * 2] * inv, es[i * 2 + 1] * inv);
    ((uint4*)row)[tid] = outr;
}

// ---------------- launch ----------------
extern "C" void kernel_launch(void* const* d_in, const int* in_sizes, int n_in,
                              void* d_out, int out_size) {
    (void)in_sizes; (void)n_in; (void)out_size;
    const float* inq  = (const float*)d_in[0];
    const float* ink  = (const float*)d_in[1];
    const float* invv = (const float*)d_in[2];
    const int*   mask = (const int*)d_in[3];
    const float* prop = (const float*)d_in[4];
    const float* Wq = (const float*)d_in[5];
    const float* bq = (const float*)d_in[6];
    const float* Wk = (const float*)d_in[7];
    const float* bk = (const float*)d_in[8];
    const float* Wv = (const float*)d_in[9];
    const float* bv = (const float*)d_in[10];
    const float* Wo = (const float*)d_in[11];
    const float* bo = (const float*)d_in[12];

    __half *Xq, *Xk, *Xv, *Qh, *Kh, *Vt, *Oh, *Ph, *Wqt, *Wkt, *Wvt, *Wot, *S1, *S2;
    cudaGetSymbolAddress((void**)&Xq, g_Xq);
    cudaGetSymbolAddress((void**)&Xk, g_Xk);
    cudaGetSymbolAddress((void**)&Xv, g_Xv);
    cudaGetSymbolAddress((void**)&Qh, g_Qh);
    cudaGetSymbolAddress((void**)&Kh, g_Kh);
    cudaGetSymbolAddress((void**)&Vt, g_Vt);
    cudaGetSymbolAddress((void**)&Oh, g_Oh);
    cudaGetSymbolAddress((void**)&Ph, g_Ph);
    cudaGetSymbolAddress((void**)&Wqt, g_Wqt);
    cudaGetSymbolAddress((void**)&Wkt, g_Wkt);
    cudaGetSymbolAddress((void**)&Wvt, g_Wvt);
    cudaGetSymbolAddress((void**)&Wot, g_Wot);
    cudaGetSymbolAddress((void**)&S1, g_S1);
    cudaGetSymbolAddress((void**)&S2, g_S2);

    dim3 blk(256);

    // 0: conversions
    {
        const long nIn = (long)B_ * S_ * D_;          // 4M
        cvt_k<<<(int)(nIn / 1024), blk>>>((const float4*)inq,  (uint2*)Xq);
        cvt_k<<<(int)(nIn / 1024), blk>>>((const float4*)ink,  (uint2*)Xk);
        cvt_k<<<(int)(nIn / 1024), blk>>>((const float4*)invv, (uint2*)Xv);
        cvt_k<<<(int)(((long)S_ * S_) / 1024), blk>>>((const float4*)prop, (uint2*)Ph);
        dim3 tg(32, 8), tgr(D_ / 32, D_ / 32);
        tr_k<<<tgr, tg>>>(Wq, Wqt);
        tr_k<<<tgr, tg>>>(Wk, Wkt);
        tr_k<<<tgr, tg>>>(Wv, Wvt);
        tr_k<<<tgr, tg>>>(Wo, Wot);
    }

    // 1-3: projections  (NT, K=1024)
    {
        HP p{};
        p.lda = D_; p.ldb = D_; p.ldc = D_;
        p.K = D_;
        dim3 grid(D_ / 128, (B_ * S_) / 128, 1);
        p.A = Xq; p.Bm = Wqt; p.bias = bq; p.C = Qh;
        gemm_h<128, 128, 32, 2, 4, 1><<<grid, blk>>>(p);
        p.A = Xk; p.Bm = Wkt; p.bias = bk; p.C = Kh;
        gemm_h<128, 128, 32, 2, 4, 1><<<grid, blk>>>(p);
        p.A = Xv; p.Bm = Wvt; p.bias = bv; p.C = Vt;   // transposed V store
        gemm_h<128, 128, 32, 2, 4, 3><<<grid, blk>>>(p);
    }

    // 4: S1 = mask ? (Q.K^T)/8 : 0   (batched NT, K=64)
    {
        HP p{};
        p.A = Qh; p.lda = D_; p.Ab = (long)S_ * D_; p.Ah = DK_;
        p.Bm = Kh; p.ldb = D_; p.Bb = (long)S_ * D_; p.Bh = DK_;
        p.C = S1; p.ldc = S_; p.Cb = (long)H_ * S_ * S_; p.Ch = (long)S_ * S_;
        p.mask = mask; p.maskB = (long)S_ * S_;
        p.scale = 0.125f;
        p.K = DK_;
        dim3 grid(S_ / 128, S_ / 128, B_ * H_);
        gemm_h<128, 128, 32, 2, 4, 2><<<grid, blk>>>(p);
    }

    // 5: S2 = S1 @ P^T   (batched NT, K=2048 — dominant GEMM)
    {
        HP p{};
        p.A = S1; p.lda = S_; p.Ab = (long)H_ * S_ * S_; p.Ah = (long)S_ * S_;
        p.Bm = Ph; p.ldb = S_;
        p.C = S2; p.ldc = S_; p.Cb = (long)H_ * S_ * S_; p.Ch = (long)S_ * S_;
        p.K = S_;
        dim3 grid(S_ / 128, S_ / 128, B_ * H_);
        gemm_h<128, 128, 32, 2, 4, 0><<<grid, blk>>>(p);
    }

    // 6: masked softmax + nan_to_num (in place, fp16)
    softmax_h<<<B_ * H_ * S_, 256>>>(S2, mask);

    // 7: Oh = probs @ V   (batched NT vs Vt, N=64, K=2048)
    {
        HP p{};
        p.A = S2; p.lda = S_; p.Ab = (long)H_ * S_ * S_; p.Ah = (long)S_ * S_;
        p.Bm = Vt; p.ldb = S_; p.Bb = (long)H_ * DK_ * S_; p.Bh = (long)DK_ * S_;
        p.C = Oh; p.ldc = D_; p.Cb = (long)S_ * D_; p.Ch = DK_;
        p.K = S_;
        dim3 grid(1, S_ / 128, B_ * H_);
        gemm_h<128, 64, 32, 4, 2, 0><<<grid, blk>>>(p);
    }

    // 8: out = Oh @ Wo + bo   (NT, fp32 store)
    {
        HP p{};
        p.A = Oh; p.lda = D_;
        p.Bm = Wot; p.ldb = D_;
        p.bias = bo;
        p.C = d_out; p.ldc = D_;
        p.K = D_;
        dim3 grid(D_ / 128, (B_ * S_) / 128, 1);
        gemm_h<128, 128, 32, 2, 4, 4><<<grid, blk>>>(p);
    }
}

// round 7
// speedup vs baseline: 2.5915x; 1.3474x over previous
#include <cuda_runtime.h>
#include <cuda_fp16.h>
#include <cstdint>

#define B_  2
#define S_  2048
#define D_  1024
#define H_  16
#define DK_ 64

typedef unsigned int u32;

// ---------------- scratch (device globals: allocation-free) ----------------
__device__ __half g_Xq[(size_t)B_ * S_ * D_];      // fp16 inputs (8 MB each)
__device__ __half g_Xk[(size_t)B_ * S_ * D_];
__device__ __half g_Xv[(size_t)B_ * S_ * D_];
__device__ __half g_Qh[(size_t)B_ * S_ * D_];      // projected Q/K
__device__ __half g_Kh[(size_t)B_ * S_ * D_];
__device__ __half g_Vt[(size_t)B_ * S_ * D_];      // V transposed [b][h][dk][S]
__device__ __half g_Oh[(size_t)B_ * S_ * D_];      // attention output (pre Wo)
__device__ __half g_Ph[(size_t)S_ * S_];           // fp16 propagation matrix
__device__ __half g_Wqt[(size_t)D_ * D_];          // transposed fp16 weights [N][K]
__device__ __half g_Wkt[(size_t)D_ * D_];
__device__ __half g_Wvt[(size_t)D_ * D_];
__device__ __half g_Wot[(size_t)D_ * D_];
__device__ __half g_S1[(size_t)B_ * H_ * S_ * S_]; // 256 MB
__device__ __half g_S2[(size_t)B_ * H_ * S_ * S_]; // 256 MB

// ---------------- asm helpers ----------------
__device__ __forceinline__ void mma16(float* c, const u32* a, const u32* b) {
    asm volatile(
        "mma.sync.aligned.m16n8k16.row.col.f32.f16.f16.f32 "
        "{%0,%1,%2,%3},{%4,%5,%6,%7},{%8,%9},{%0,%1,%2,%3};\n"
        : "+f"(c[0]), "+f"(c[1]), "+f"(c[2]), "+f"(c[3])
        : "r"(a[0]), "r"(a[1]), "r"(a[2]), "r"(a[3]), "r"(b[0]), "r"(b[1]));
}

__device__ __forceinline__ void ldsm4(u32& r0, u32& r1, u32& r2, u32& r3, u32 a) {
    asm volatile("ldmatrix.sync.aligned.m8n8.x4.shared.b16 {%0,%1,%2,%3}, [%4];"
                 : "=r"(r0), "=r"(r1), "=r"(r2), "=r"(r3) : "r"(a));
}

__device__ __forceinline__ u32 smem_u32(const void* p) {
    u32 a;
    asm("{ .reg .u64 t; cvta.to.shared.u64 t, %1; cvt.u32.u64 %0, t; }"
        : "=r"(a) : "l"(p));
    return a;
}

__device__ __forceinline__ void cpa16(u32 dst, const void* src) {
    asm volatile("cp.async.cg.shared.global [%0], [%1], 16;" :: "r"(dst), "l"(src));
}
#define CP_COMMIT() asm volatile("cp.async.commit_group;" ::: "memory")

struct HP {
    const __half* A;
    const __half* Bm;
    void*         C;
    const float*  bias;   // EPI 1/3/4
    const int*    mask;   // EPI 2
    long lda, ldb, ldc;
    long Ab, Ah, Bb, Bh, Cb, Ch, maskB;
    float scale;
    int  K;
};

// ---------------- fp16 NT GEMM: cp.async pipeline + ldmatrix + m16n8k16 -----
// C[m][n] = sum_k A[m][k]*B[n][k], A/B K-contiguous fp16, BK = 64 halves (128B).
// EPI: 0 plain fp16, 1 +bias fp16, 2 mask?v*scale:0 fp16,
//      3 +bias V-transposed fp16, 4 +bias fp32
template<int BM, int BN, int WMN, int WNN, int EPI, int STAGES>
__global__ __launch_bounds__(256) void gemm_l(HP p) {
    static_assert(WMN * WNN == 8, "8 warps");
    constexpr int WTM  = BM / WMN;
    constexpr int WTN  = BN / WNN;
    constexpr int MT   = WTM / 16;
    constexpr int NTj  = WTN / 8;
    constexpr int STGB = (BM + BN) * 128;          // stage bytes
    constexpr int CHK  = (BM + BN) * 8 / 256;      // 16B chunks per thread

    extern __shared__ __align__(1024) char smem[];
    const u32 sb = smem_u32(smem);

    const int tid  = threadIdx.x;
    const int wid  = tid >> 5, lane = tid & 31;
    const int wm   = wid / WNN, wn = wid % WNN;
    const int g    = lane >> 2, tg = lane & 3;
    const int z    = blockIdx.z;
    const int b    = z / H_, h = z % H_;

    const __half* Ab = p.A + (long)b * p.Ab + (long)h * p.Ah
                           + (long)blockIdx.y * BM * p.lda;
    const __half* Bb = p.Bm + (long)b * p.Bb + (long)h * p.Bh
                            + (long)blockIdx.x * BN * p.ldb;

    const int KT = p.K >> 6;

    // cp.async chunk coords for this thread
    int cR[CHK], cC[CHK];
#pragma unroll
    for (int i = 0; i < CHK; i++) {
        int id = tid + i * 256;
        cR[i] = id >> 3;
        cC[i] = id & 7;
    }

    auto loadStage = [&](int kt) {
        if (kt < KT) {
            const u32 s0 = sb + (kt % STAGES) * STGB;
#pragma unroll
            for (int i = 0; i < CHK; i++) {
                int r = cR[i], c = cC[i];
                if (r < BM) {
                    cpa16(s0 + r * 128 + ((c ^ (r & 7)) << 4),
                          Ab + (long)r * p.lda + kt * 64 + c * 8);
                } else {
                    int rr = r - BM;
                    cpa16(s0 + BM * 128 + rr * 128 + ((c ^ (rr & 7)) << 4),
                          Bb + (long)rr * p.ldb + kt * 64 + c * 8);
                }
            }
        }
        CP_COMMIT();
    };

    // ldmatrix per-thread row precompute
    const int la    = lane & 7;
    const int ksegA = (lane >> 4) & 1;
    const int ksegB = (lane >> 3) & 1;
    int aRow[MT], aSw[MT], bRow[NTj / 2], bSw[NTj / 2];
#pragma unroll
    for (int i = 0; i < MT; i++) {
        int r = wm * WTM + i * 16 + ((lane >> 3) & 1) * 8 + la;
        aRow[i] = r * 128;
        aSw[i]  = r & 7;
    }
#pragma unroll
    for (int j = 0; j < NTj / 2; j++) {
        int r = wn * WTN + j * 16 + ((lane >> 4) & 1) * 8 + la;
        bRow[j] = r * 128;
        bSw[j]  = r & 7;
    }

    float acc[MT][NTj][4];
#pragma unroll
    for (int i = 0; i < MT; i++)
#pragma unroll
        for (int j = 0; j < NTj; j++)
#pragma unroll
            for (int k = 0; k < 4; k++) acc[i][j][k] = 0.f;

#pragma unroll
    for (int s = 0; s < STAGES - 1; s++) loadStage(s);

    for (int kt = 0; kt < KT; kt++) {
        asm volatile("cp.async.wait_group %0;" :: "n"(STAGES - 2));
        __syncthreads();
        loadStage(kt + STAGES - 1);

        const u32 sA = sb + (kt % STAGES) * STGB;
        const u32 sB = sA + BM * 128;
#pragma unroll
        for (int ks = 0; ks < 4; ks++) {
            u32 af[MT][4], bf[NTj][2];
            const int ca = ks * 2 + ksegA;
            const int cb = ks * 2 + ksegB;
#pragma unroll
            for (int i = 0; i < MT; i++)
                ldsm4(af[i][0], af[i][1], af[i][2], af[i][3],
                      sA + aRow[i] + ((ca ^ aSw[i]) << 4));
#pragma unroll
            for (int j = 0; j < NTj / 2; j++)
                ldsm4(bf[2 * j][0], bf[2 * j][1], bf[2 * j + 1][0], bf[2 * j + 1][1],
                      sB + bRow[j] + ((cb ^ bSw[j]) << 4));
#pragma unroll
            for (int i = 0; i < MT; i++)
#pragma unroll
                for (int j = 0; j < NTj; j++)
                    mma16(acc[i][j], af[i], bf[j]);
        }
        __syncthreads();
    }

    // ---------------- epilogue ----------------
    const long row0 = (long)blockIdx.y * BM + wm * WTM;
    const long col0 = (long)blockIdx.x * BN + wn * WTN;

#pragma unroll
    for (int i = 0; i < MT; i++) {
        const long r0 = row0 + i * 16 + g;
#pragma unroll
        for (int j = 0; j < NTj; j++) {
            const long c = col0 + j * 8 + tg * 2;
            float v0 = acc[i][j][0], v1 = acc[i][j][1];
            float v2 = acc[i][j][2], v3 = acc[i][j][3];
            if constexpr (EPI == 1 || EPI == 3 || EPI == 4) {
                float b0 = p.bias[c], b1 = p.bias[c + 1];
                v0 += b0; v1 += b1; v2 += b0; v3 += b1;
            }
            if constexpr (EPI == 2) {
                const int* mb = p.mask + (long)b * p.maskB;
                const int2 m01 = *(const int2*)(mb + r0 * S_ + c);
                const int2 m23 = *(const int2*)(mb + (r0 + 8) * S_ + c);
                v0 = m01.x ? v0 * p.scale : 0.f;
                v1 = m01.y ? v1 * p.scale : 0.f;
                v2 = m23.x ? v2 * p.scale : 0.f;
                v3 = m23.y ? v3 * p.scale : 0.f;
            }
            if constexpr (EPI == 3) {
                // Vt[((b*H + h)*64 + d)*S + s]
                __half* Ct = (__half*)p.C;
                const int hh = (int)(c >> 6), d = (int)(c & 63);
                {
                    const long bb = r0 >> 11, s = r0 & (S_ - 1);
                    __half* base = Ct + ((bb * H_ + hh) * 64 + d) * (long)S_ + s;
                    base[0]  = __float2half_rn(v0);
                    base[S_] = __float2half_rn(v1);
                }
                {
                    const long bb = (r0 + 8) >> 11, s = (r0 + 8) & (S_ - 1);
                    __half* base = Ct + ((bb * H_ + hh) * 64 + d) * (long)S_ + s;
                    base[0]  = __float2half_rn(v2);
                    base[S_] = __float2half_rn(v3);
                }
            } else if constexpr (EPI == 4) {
                float* C = (float*)p.C + (long)b * p.Cb + (long)h * p.Ch;
                *(float2*)(C + r0 * p.ldc + c)       = make_float2(v0, v1);
                *(float2*)(C + (r0 + 8) * p.ldc + c) = make_float2(v2, v3);
            } else {
                __half* C = (__half*)p.C + (long)b * p.Cb + (long)h * p.Ch;
                *(__half2*)(C + r0 * p.ldc + c)       = __floats2half2_rn(v0, v1);
                *(__half2*)(C + (r0 + 8) * p.ldc + c) = __floats2half2_rn(v2, v3);
            }
        }
    }
}

// ---------------- fp32 -> fp16 copy (4 elements / thread) ----------------
__global__ __launch_bounds__(256) void cvt_k(const float4* __restrict__ in,
                                             uint2* __restrict__ out) {
    long i = (long)blockIdx.x * 256 + threadIdx.x;
    float4 v = in[i];
    __half2 lo = __floats2half2_rn(v.x, v.y);
    __half2 hi = __floats2half2_rn(v.z, v.w);
    out[i] = make_uint2(*(u32*)&lo, *(u32*)&hi);
}

// ---------------- fp32 [K][N] -> fp16 [N][K] transpose (1024x1024) -----------
__global__ __launch_bounds__(256) void tr_k(const float* __restrict__ in,
                                            __half* __restrict__ out) {
    __shared__ float t[32][33];
    const int bx = blockIdx.x * 32, by = blockIdx.y * 32;
    const int x = threadIdx.x, y0 = threadIdx.y * 4;
#pragma unroll
    for (int i = 0; i < 4; i++)
        t[y0 + i][x] = in[(long)(by + y0 + i) * D_ + bx + x];
    __syncthreads();
#pragma unroll
    for (int i = 0; i < 4; i++)
        out[(long)(bx + y0 + i) * D_ + by + x] = __float2half_rn(t[x][y0 + i]);
}

// ---------------- masked softmax + nan_to_num, fp16 in-place ----------------
__global__ __launch_bounds__(256) void softmax_h(__half* __restrict__ S,
                                                 const int* __restrict__ mask) {
    const long r  = blockIdx.x;                 // [0, B*H*S)
    const int  q  = (int)(r & (S_ - 1));
    const int  bh = (int)(r >> 11);
    const int  b  = bh >> 4;
    __half* row = S + r * (long)S_;
    const int* mrow = mask + ((long)b * S_ + q) * (long)S_;
    const int tid = threadIdx.x;

    uint4 xr = ((const uint4*)row)[tid];        // 8 halves
    int4  m0 = ((const int4*)mrow)[2 * tid];
    int4  m1 = ((const int4*)mrow)[2 * tid + 1];
    const __half2* hp = (const __half2*)&xr;
    float xs[8];
#pragma unroll
    for (int i = 0; i < 4; i++) {
        float2 f = __half22float2(hp[i]);
        xs[i * 2] = f.x; xs[i * 2 + 1] = f.y;
    }
    int ms[8] = {m0.x, m0.y, m0.z, m0.w, m1.x, m1.y, m1.z, m1.w};

    float lmax = -3.402823466e38f;
#pragma unroll
    for (int i = 0; i < 8; i++)
        if (ms[i]) lmax = fmaxf(lmax, xs[i]);
#pragma unroll
    for (int o = 16; o > 0; o >>= 1)
        lmax = fmaxf(lmax, __shfl_xor_sync(0xffffffffu, lmax, o));

    __shared__ float sm[8];
    if ((tid & 31) == 0) sm[tid >> 5] = lmax;
    __syncthreads();
    float bmax = sm[0];
#pragma unroll
    for (int i = 1; i < 8; i++) bmax = fmaxf(bmax, sm[i]);
    __syncthreads();

    float es[8];
    float lsum = 0.f;
#pragma unroll
    for (int i = 0; i < 8; i++) {
        es[i] = ms[i] ? expf(xs[i] - bmax) : 0.f;
        lsum += es[i];
    }
#pragma unroll
    for (int o = 16; o > 0; o >>= 1)
        lsum += __shfl_xor_sync(0xffffffffu, lsum, o);
    if ((tid & 31) == 0) sm[tid >> 5] = lsum;
    __syncthreads();
    float bsum = 0.f;
#pragma unroll
    for (int i = 0; i < 8; i++) bsum += sm[i];

    const float inv = (bsum > 0.f) ? 1.f / bsum : 0.f;
    uint4 outr;
    __half2* op = (__half2*)&outr;
#pragma unroll
    for (int i = 0; i < 4; i++)
        op[i] = __floats2half2_rn(es[i * 2] * inv, es[i * 2 + 1] * inv);
    ((uint4*)row)[tid] = outr;
}

// ---------------- launch ----------------
#define SMEM_BIG (4 * (128 + 256) * 128)   // 196608
#define SMEM_AV  (4 * (128 + 64) * 128)    //  98304

extern "C" void kernel_launch(void* const* d_in, const int* in_sizes, int n_in,
                              void* d_out, int out_size) {
    (void)in_sizes; (void)n_in; (void)out_size;
    const float* inq  = (const float*)d_in[0];
    const float* ink  = (const float*)d_in[1];
    const float* invv = (const float*)d_in[2];
    const int*   mask = (const int*)d_in[3];
    const float* prop = (const float*)d_in[4];
    const float* Wq = (const float*)d_in[5];
    const float* bq = (const float*)d_in[6];
    const float* Wk = (const float*)d_in[7];
    const float* bk = (const float*)d_in[8];
    const float* Wv = (const float*)d_in[9];
    const float* bv = (const float*)d_in[10];
    const float* Wo = (const float*)d_in[11];
    const float* bo = (const float*)d_in[12];

    __half *Xq, *Xk, *Xv, *Qh, *Kh, *Vt, *Oh, *Ph, *Wqt, *Wkt, *Wvt, *Wot, *S1, *S2;
    cudaGetSymbolAddress((void**)&Xq, g_Xq);
    cudaGetSymbolAddress((void**)&Xk, g_Xk);
    cudaGetSymbolAddress((void**)&Xv, g_Xv);
    cudaGetSymbolAddress((void**)&Qh, g_Qh);
    cudaGetSymbolAddress((void**)&Kh, g_Kh);
    cudaGetSymbolAddress((void**)&Vt, g_Vt);
    cudaGetSymbolAddress((void**)&Oh, g_Oh);
    cudaGetSymbolAddress((void**)&Ph, g_Ph);
    cudaGetSymbolAddress((void**)&Wqt, g_Wqt);
    cudaGetSymbolAddress((void**)&Wkt, g_Wkt);
    cudaGetSymbolAddress((void**)&Wvt, g_Wvt);
    cudaGetSymbolAddress((void**)&Wot, g_Wot);
    cudaGetSymbolAddress((void**)&S1, g_S1);
    cudaGetSymbolAddress((void**)&S2, g_S2);

    cudaFuncSetAttribute((gemm_l<128, 256, 2, 4, 0, 4>), cudaFuncAttributeMaxDynamicSharedMemorySize, SMEM_BIG);
    cudaFuncSetAttribute((gemm_l<128, 256, 2, 4, 1, 4>), cudaFuncAttributeMaxDynamicSharedMemorySize, SMEM_BIG);
    cudaFuncSetAttribute((gemm_l<128, 256, 2, 4, 2, 4>), cudaFuncAttributeMaxDynamicSharedMemorySize, SMEM_BIG);
    cudaFuncSetAttribute((gemm_l<128, 256, 2, 4, 3, 4>), cudaFuncAttributeMaxDynamicSharedMemorySize, SMEM_BIG);
    cudaFuncSetAttribute((gemm_l<128, 256, 2, 4, 4, 4>), cudaFuncAttributeMaxDynamicSharedMemorySize, SMEM_BIG);
    cudaFuncSetAttribute((gemm_l<128, 64, 4, 2, 0, 4>),  cudaFuncAttributeMaxDynamicSharedMemorySize, SMEM_AV);

    dim3 blk(256);

    // 0: conversions
    {
        const long nIn = (long)B_ * S_ * D_;          // 4M
        cvt_k<<<(int)(nIn / 1024), blk>>>((const float4*)inq,  (uint2*)Xq);
        cvt_k<<<(int)(nIn / 1024), blk>>>((const float4*)ink,  (uint2*)Xk);
        cvt_k<<<(int)(nIn / 1024), blk>>>((const float4*)invv, (uint2*)Xv);
        cvt_k<<<(int)(((long)S_ * S_) / 1024), blk>>>((const float4*)prop, (uint2*)Ph);
        dim3 tg(32, 8), tgr(D_ / 32, D_ / 32);
        tr_k<<<tgr, tg>>>(Wq, Wqt);
        tr_k<<<tgr, tg>>>(Wk, Wkt);
        tr_k<<<tgr, tg>>>(Wv, Wvt);
        tr_k<<<tgr, tg>>>(Wo, Wot);
    }

    // 1-3: projections (NT, K=1024)
    {
        HP p{};
        p.lda = D_; p.ldb = D_; p.ldc = D_;
        p.K = D_;
        dim3 grid(D_ / 256, (B_ * S_) / 128, 1);
        p.A = Xq; p.Bm = Wqt; p.bias = bq; p.C = Qh;
        gemm_l<128, 256, 2, 4, 1, 4><<<grid, blk, SMEM_BIG>>>(p);
        p.A = Xk; p.Bm = Wkt; p.bias = bk; p.C = Kh;
        gemm_l<128, 256, 2, 4, 1, 4><<<grid, blk, SMEM_BIG>>>(p);
        p.A = Xv; p.Bm = Wvt; p.bias = bv; p.C = Vt;   // transposed V store
        gemm_l<128, 256, 2, 4, 3, 4><<<grid, blk, SMEM_BIG>>>(p);
    }

    // 4: S1 = mask ? (Q.K^T)/8 : 0   (batched NT, K=64)
    {
        HP p{};
        p.A = Qh; p.lda = D_; p.Ab = (long)S_ * D_; p.Ah = DK_;
        p.Bm = Kh; p.ldb = D_; p.Bb = (long)S_ * D_; p.Bh = DK_;
        p.C = S1; p.ldc = S_; p.Cb = (long)H_ * S_ * S_; p.Ch = (long)S_ * S_;
        p.mask = mask; p.maskB = (long)S_ * S_;
        p.scale = 0.125f;
        p.K = DK_;
        dim3 grid(S_ / 256, S_ / 128, B_ * H_);
        gemm_l<128, 256, 2, 4, 2, 4><<<grid, blk, SMEM_BIG>>>(p);
    }

    // 5: S2 = S1 @ P^T   (batched NT, K=2048 — dominant GEMM)
    {
        HP p{};
        p.A = S1; p.lda = S_; p.Ab = (long)H_ * S_ * S_; p.Ah = (long)S_ * S_;
        p.Bm = Ph; p.ldb = S_;
        p.C = S2; p.ldc = S_; p.Cb = (long)H_ * S_ * S_; p.Ch = (long)S_ * S_;
        p.K = S_;
        dim3 grid(S_ / 256, S_ / 128, B_ * H_);
        gemm_l<128, 256, 2, 4, 0, 4><<<grid, blk, SMEM_BIG>>>(p);
    }

    // 6: masked softmax + nan_to_num (in place, fp16)
    softmax_h<<<B_ * H_ * S_, 256>>>(S2, mask);

    // 7: Oh = probs @ V   (batched NT vs Vt, N=64, K=2048)
    {
        HP p{};
        p.A = S2; p.lda = S_; p.Ab = (long)H_ * S_ * S_; p.Ah = (long)S_ * S_;
        p.Bm = Vt; p.ldb = S_; p.Bb = (long)H_ * DK_ * S_; p.Bh = (long)DK_ * S_;
        p.C = Oh; p.ldc = D_; p.Cb = (long)S_ * D_; p.Ch = DK_;
        p.K = S_;
        dim3 grid(1, S_ / 128, B_ * H_);
        gemm_l<128, 64, 4, 2, 0, 4><<<grid, blk, SMEM_AV>>>(p);
    }

    // 8: out = Oh @ Wo + bo   (NT, fp32 store)
    {
        HP p{};
        p.A = Oh; p.lda = D_;
        p.Bm = Wot; p.ldb = D_;
        p.bias = bo;
        p.C = d_out; p.ldc = D_;
        p.K = D_;
        dim3 grid(D_ / 256, (B_ * S_) / 128, 1);
        gemm_l<128, 256, 2, 4, 4, 4><<<grid, blk, SMEM_BIG>>>(p);
    }
}

// round 8
// speedup vs baseline: 2.6622x; 1.0273x over previous
#include <cuda_runtime.h>
#include <cuda_fp16.h>
#include <cstdint>

#define B_  2
#define S_  2048
#define D_  1024
#define H_  16
#define DK_ 64

typedef unsigned int u32;

// ---------------- scratch (device globals: allocation-free) ----------------
__device__ __half g_Xq[(size_t)B_ * S_ * D_];      // fp16 inputs (8 MB each)
__device__ __half g_Xk[(size_t)B_ * S_ * D_];
__device__ __half g_Xv[(size_t)B_ * S_ * D_];
__device__ __half g_Qh[(size_t)B_ * S_ * D_];      // projected Q/K
__device__ __half g_Kh[(size_t)B_ * S_ * D_];
__device__ __half g_Vt[(size_t)B_ * S_ * D_];      // V transposed [b][h][dk][S]
__device__ __half g_Oh[(size_t)B_ * S_ * D_];      // attention output (pre Wo)
__device__ __half g_Ph[(size_t)S_ * S_];           // fp16 propagation matrix
__device__ __half g_Wqt[(size_t)D_ * D_];          // transposed fp16 weights [N][K]
__device__ __half g_Wkt[(size_t)D_ * D_];
__device__ __half g_Wvt[(size_t)D_ * D_];
__device__ __half g_Wot[(size_t)D_ * D_];
__device__ __half g_S1[(size_t)B_ * H_ * S_ * S_]; // 256 MB
__device__ __half g_S2[(size_t)B_ * H_ * S_ * S_]; // 256 MB
__device__ u32    g_Mb[(size_t)B_ * S_ * S_ / 32]; // bitpacked mask (1 MB)

// ---------------- asm helpers ----------------
__device__ __forceinline__ void mma16(float* c, const u32* a, const u32* b) {
    asm volatile(
        "mma.sync.aligned.m16n8k16.row.col.f32.f16.f16.f32 "
        "{%0,%1,%2,%3},{%4,%5,%6,%7},{%8,%9},{%0,%1,%2,%3};\n"
        : "+f"(c[0]), "+f"(c[1]), "+f"(c[2]), "+f"(c[3])
        : "r"(a[0]), "r"(a[1]), "r"(a[2]), "r"(a[3]), "r"(b[0]), "r"(b[1]));
}

__device__ __forceinline__ void ldsm4(u32& r0, u32& r1, u32& r2, u32& r3, u32 a) {
    asm volatile("ldmatrix.sync.aligned.m8n8.x4.shared.b16 {%0,%1,%2,%3}, [%4];"
                 : "=r"(r0), "=r"(r1), "=r"(r2), "=r"(r3) : "r"(a));
}

__device__ __forceinline__ u32 smem_u32(const void* p) {
    u32 a;
    asm("{ .reg .u64 t; cvta.to.shared.u64 t, %1; cvt.u32.u64 %0, t; }"
        : "=r"(a) : "l"(p));
    return a;
}

__device__ __forceinline__ void cpa16(u32 dst, const void* src) {
    asm volatile("cp.async.cg.shared.global [%0], [%1], 16;" :: "r"(dst), "l"(src));
}
#define CP_COMMIT() asm volatile("cp.async.commit_group;" ::: "memory")

struct HP {
    const __half* A;
    const __half* Bm;
    void*         C;
    const float*  bias;   // EPI 1/3/4
    const u32*    mask;   // EPI 2 (bitpacked, 64 words per row)
    long lda, ldb, ldc;
    long Ab, Ah, Bb, Bh, Cb, Ch, maskB;
    float scale;
    int  K;
};

// ---------------- fp16 NT GEMM: cp.async pipeline + ldmatrix + m16n8k16 -----
// C[m][n] = sum_k A[m][k]*B[n][k], A/B K-contiguous fp16, BK = 64 halves (128B).
// EPI: 0 plain fp16, 1 +bias fp16, 2 maskbit?v*scale:0 fp16,
//      3 +bias V-transposed fp16, 4 +bias fp32
template<int BM, int BN, int WMN, int WNN, int EPI, int STAGES>
__global__ __launch_bounds__(256) void gemm_l(HP p) {
    static_assert(WMN * WNN == 8, "8 warps");
    constexpr int WTM  = BM / WMN;
    constexpr int WTN  = BN / WNN;
    constexpr int MT   = WTM / 16;
    constexpr int NTj  = WTN / 8;
    constexpr int STGB = (BM + BN) * 128;          // stage bytes
    constexpr int CHK  = (BM + BN) * 8 / 256;      // 16B chunks per thread

    extern __shared__ __align__(1024) char smem[];
    const u32 sb = smem_u32(smem);

    const int tid  = threadIdx.x;
    const int wid  = tid >> 5, lane = tid & 31;
    const int wm   = wid / WNN, wn = wid % WNN;
    const int g    = lane >> 2, tg = lane & 3;
    const int z    = blockIdx.z;
    const int b    = z / H_, h = z % H_;

    const __half* Ab = p.A + (long)b * p.Ab + (long)h * p.Ah
                           + (long)blockIdx.y * BM * p.lda;
    const __half* Bb = p.Bm + (long)b * p.Bb + (long)h * p.Bh
                            + (long)blockIdx.x * BN * p.ldb;

    const int KT = p.K >> 6;

    // cp.async chunk coords for this thread
    int cR[CHK], cC[CHK];
#pragma unroll
    for (int i = 0; i < CHK; i++) {
        int id = tid + i * 256;
        cR[i] = id >> 3;
        cC[i] = id & 7;
    }

    auto loadStage = [&](int kt) {
        if (kt < KT) {
            const u32 s0 = sb + (kt % STAGES) * STGB;
#pragma unroll
            for (int i = 0; i < CHK; i++) {
                int r = cR[i], c = cC[i];
                if (r < BM) {
                    cpa16(s0 + r * 128 + ((c ^ (r & 7)) << 4),
                          Ab + (long)r * p.lda + kt * 64 + c * 8);
                } else {
                    int rr = r - BM;
                    cpa16(s0 + BM * 128 + rr * 128 + ((c ^ (rr & 7)) << 4),
                          Bb + (long)rr * p.ldb + kt * 64 + c * 8);
                }
            }
        }
        CP_COMMIT();
    };

    // ldmatrix per-thread row precompute
    const int la    = lane & 7;
    const int ksegA = (lane >> 4) & 1;
    const int ksegB = (lane >> 3) & 1;
    int aRow[MT], aSw[MT], bRow[NTj / 2], bSw[NTj / 2];
#pragma unroll
    for (int i = 0; i < MT; i++) {
        int r = wm * WTM + i * 16 + ((lane >> 3) & 1) * 8 + la;
        aRow[i] = r * 128;
        aSw[i]  = r & 7;
    }
#pragma unroll
    for (int j = 0; j < NTj / 2; j++) {
        int r = wn * WTN + j * 16 + ((lane >> 4) & 1) * 8 + la;
        bRow[j] = r * 128;
        bSw[j]  = r & 7;
    }

    float acc[MT][NTj][4];
#pragma unroll
    for (int i = 0; i < MT; i++)
#pragma unroll
        for (int j = 0; j < NTj; j++)
#pragma unroll
            for (int k = 0; k < 4; k++) acc[i][j][k] = 0.f;

#pragma unroll
    for (int s = 0; s < STAGES - 1; s++) loadStage(s);

    for (int kt = 0; kt < KT; kt++) {
        asm volatile("cp.async.wait_group %0;" :: "n"(STAGES - 2));
        __syncthreads();    // single barrier per k-tile: orders last-read vs next-write
        loadStage(kt + STAGES - 1);

        const u32 sA = sb + (kt % STAGES) * STGB;
        const u32 sB = sA + BM * 128;
#pragma unroll
        for (int ks = 0; ks < 4; ks++) {
            u32 af[MT][4], bf[NTj][2];
            const int ca = ks * 2 + ksegA;
            const int cb = ks * 2 + ksegB;
#pragma unroll
            for (int i = 0; i < MT; i++)
                ldsm4(af[i][0], af[i][1], af[i][2], af[i][3],
                      sA + aRow[i] + ((ca ^ aSw[i]) << 4));
#pragma unroll
            for (int j = 0; j < NTj / 2; j++)
                ldsm4(bf[2 * j][0], bf[2 * j][1], bf[2 * j + 1][0], bf[2 * j + 1][1],
                      sB + bRow[j] + ((cb ^ bSw[j]) << 4));
#pragma unroll
            for (int i = 0; i < MT; i++)
#pragma unroll
                for (int j = 0; j < NTj; j++)
                    mma16(acc[i][j], af[i], bf[j]);
        }
    }

    // ---------------- epilogue ----------------
    const long row0 = (long)blockIdx.y * BM + wm * WTM;
    const long col0 = (long)blockIdx.x * BN + wn * WTN;

#pragma unroll
    for (int i = 0; i < MT; i++) {
        const long r0 = row0 + i * 16 + g;
#pragma unroll
        for (int j = 0; j < NTj; j++) {
            const long c = col0 + j * 8 + tg * 2;
            float v0 = acc[i][j][0], v1 = acc[i][j][1];
            float v2 = acc[i][j][2], v3 = acc[i][j][3];
            if constexpr (EPI == 1 || EPI == 3 || EPI == 4) {
                float b0 = p.bias[c], b1 = p.bias[c + 1];
                v0 += b0; v1 += b1; v2 += b0; v3 += b1;
            }
            if constexpr (EPI == 2) {
                const u32* mb = p.mask + (long)b * p.maskB;
                const int   wofs = (int)(c >> 5), sh = (int)(c & 31);
                u32 w0 = mb[r0 * (S_ / 32) + wofs];
                u32 w1 = mb[(r0 + 8) * (S_ / 32) + wofs];
                v0 = (w0 >> sh) & 1       ? v0 * p.scale : 0.f;
                v1 = (w0 >> (sh + 1)) & 1 ? v1 * p.scale : 0.f;
                v2 = (w1 >> sh) & 1       ? v2 * p.scale : 0.f;
                v3 = (w1 >> (sh + 1)) & 1 ? v3 * p.scale : 0.f;
            }
            if constexpr (EPI == 3) {
                // Vt[((b*H + h)*64 + d)*S + s]
                __half* Ct = (__half*)p.C;
                const int hh = (int)(c >> 6), d = (int)(c & 63);
                {
                    const long bb = r0 >> 11, s = r0 & (S_ - 1);
                    __half* base = Ct + ((bb * H_ + hh) * 64 + d) * (long)S_ + s;
                    base[0]  = __float2half_rn(v0);
                    base[S_] = __float2half_rn(v1);
                }
                {
                    const long bb = (r0 + 8) >> 11, s = (r0 + 8) & (S_ - 1);
                    __half* base = Ct + ((bb * H_ + hh) * 64 + d) * (long)S_ + s;
                    base[0]  = __float2half_rn(v2);
                    base[S_] = __float2half_rn(v3);
                }
            } else if constexpr (EPI == 4) {
                float* C = (float*)p.C + (long)b * p.Cb + (long)h * p.Ch;
                *(float2*)(C + r0 * p.ldc + c)       = make_float2(v0, v1);
                *(float2*)(C + (r0 + 8) * p.ldc + c) = make_float2(v2, v3);
            } else {
                __half* C = (__half*)p.C + (long)b * p.Cb + (long)h * p.Ch;
                *(__half2*)(C + r0 * p.ldc + c)       = __floats2half2_rn(v0, v1);
                *(__half2*)(C + (r0 + 8) * p.ldc + c) = __floats2half2_rn(v2, v3);
            }
        }
    }
}

// ---------------- mask bitpack: one warp ballot per 32 ints ----------------
__global__ __launch_bounds__(256) void pack_k(const int* __restrict__ mask,
                                              u32* __restrict__ out) {
    const long i = (long)blockIdx.x * 256 + threadIdx.x;   // over all B*S*S
    const int  m = mask[i];
    const u32  w = __ballot_sync(0xffffffffu, m != 0);
    if ((threadIdx.x & 31) == 0) out[i >> 5] = w;
}

// ---------------- fp32 -> fp16 copy (4 elements / thread) ----------------
__global__ __launch_bounds__(256) void cvt_k(const float4* __restrict__ in,
                                             uint2* __restrict__ out) {
    long i = (long)blockIdx.x * 256 + threadIdx.x;
    float4 v = in[i];
    __half2 lo = __floats2half2_rn(v.x, v.y);
    __half2 hi = __floats2half2_rn(v.z, v.w);
    out[i] = make_uint2(*(u32*)&lo, *(u32*)&hi);
}

// ---------------- fp32 [K][N] -> fp16 [N][K] transpose (1024x1024) -----------
__global__ __launch_bounds__(256) void tr_k(const float* __restrict__ in,
                                            __half* __restrict__ out) {
    __shared__ float t[32][33];
    const int bx = blockIdx.x * 32, by = blockIdx.y * 32;
    const int x = threadIdx.x, y0 = threadIdx.y * 4;
#pragma unroll
    for (int i = 0; i < 4; i++)
        t[y0 + i][x] = in[(long)(by + y0 + i) * D_ + bx + x];
    __syncthreads();
#pragma unroll
    for (int i = 0; i < 4; i++)
        out[(long)(bx + y0 + i) * D_ + by + x] = __float2half_rn(t[x][y0 + i]);
}

// ---------------- masked softmax + nan_to_num, fp16 in-place, bit mask -------
__global__ __launch_bounds__(256) void softmax_h(__half* __restrict__ S,
                                                 const u32* __restrict__ maskb) {
    const long r  = blockIdx.x;                 // [0, B*H*S)
    const int  q  = (int)(r & (S_ - 1));
    const int  bh = (int)(r >> 11);
    const int  b  = bh >> 4;
    __half* row = S + r * (long)S_;
    const u32* mrow = maskb + ((long)b * S_ + q) * (S_ / 32);
    const int tid = threadIdx.x;

    uint4 xr = ((const uint4*)row)[tid];        // 8 halves
    const u32 mw   = mrow[tid >> 2];
    const u32 mbits = (mw >> ((tid & 3) * 8)) & 0xFFu;
    const __half2* hp = (const __half2*)&xr;
    float xs[8];
#pragma unroll
    for (int i = 0; i < 4; i++) {
        float2 f = __half22float2(hp[i]);
        xs[i * 2] = f.x; xs[i * 2 + 1] = f.y;
    }

    float lmax = -3.402823466e38f;
#pragma unroll
    for (int i = 0; i < 8; i++)
        if ((mbits >> i) & 1) lmax = fmaxf(lmax, xs[i]);
#pragma unroll
    for (int o = 16; o > 0; o >>= 1)
        lmax = fmaxf(lmax, __shfl_xor_sync(0xffffffffu, lmax, o));

    __shared__ float sm[8];
    if ((tid & 31) == 0) sm[tid >> 5] = lmax;
    __syncthreads();
    float bmax = sm[0];
#pragma unroll
    for (int i = 1; i < 8; i++) bmax = fmaxf(bmax, sm[i]);
    __syncthreads();

    float es[8];
    float lsum = 0.f;
#pragma unroll
    for (int i = 0; i < 8; i++) {
        es[i] = ((mbits >> i) & 1) ? expf(xs[i] - bmax) : 0.f;
        lsum += es[i];
    }
#pragma unroll
    for (int o = 16; o > 0; o >>= 1)
        lsum += __shfl_xor_sync(0xffffffffu, lsum, o);
    if ((tid & 31) == 0) sm[tid >> 5] = lsum;
    __syncthreads();
    float bsum = 0.f;
#pragma unroll
    for (int i = 0; i < 8; i++) bsum += sm[i];

    const float inv = (bsum > 0.f) ? 1.f / bsum : 0.f;
    uint4 outr;
    __half2* op = (__half2*)&outr;
#pragma unroll
    for (int i = 0; i < 4; i++)
        op[i] = __floats2half2_rn(es[i * 2] * inv, es[i * 2 + 1] * inv);
    ((uint4*)row)[tid] = outr;
}

// ---------------- launch ----------------
#define SMEM_BIG (4 * (128 + 256) * 128)   // 196608
#define SMEM_AV  (4 * (128 + 64) * 128)    //  98304

extern "C" void kernel_launch(void* const* d_in, const int* in_sizes, int n_in,
                              void* d_out, int out_size) {
    (void)in_sizes; (void)n_in; (void)out_size;
    const float* inq  = (const float*)d_in[0];
    const float* ink  = (const float*)d_in[1];
    const float* invv = (const float*)d_in[2];
    const int*   mask = (const int*)d_in[3];
    const float* prop = (const float*)d_in[4];
    const float* Wq = (const float*)d_in[5];
    const float* bq = (const float*)d_in[6];
    const float* Wk = (const float*)d_in[7];
    const float* bk = (const float*)d_in[8];
    const float* Wv = (const float*)d_in[9];
    const float* bv = (const float*)d_in[10];
    const float* Wo = (const float*)d_in[11];
    const float* bo = (const float*)d_in[12];

    __half *Xq, *Xk, *Xv, *Qh, *Kh, *Vt, *Oh, *Ph, *Wqt, *Wkt, *Wvt, *Wot, *S1, *S2;
    u32* Mb;
    cudaGetSymbolAddress((void**)&Xq, g_Xq);
    cudaGetSymbolAddress((void**)&Xk, g_Xk);
    cudaGetSymbolAddress((void**)&Xv, g_Xv);
    cudaGetSymbolAddress((void**)&Qh, g_Qh);
    cudaGetSymbolAddress((void**)&Kh, g_Kh);
    cudaGetSymbolAddress((void**)&Vt, g_Vt);
    cudaGetSymbolAddress((void**)&Oh, g_Oh);
    cudaGetSymbolAddress((void**)&Ph, g_Ph);
    cudaGetSymbolAddress((void**)&Wqt, g_Wqt);
    cudaGetSymbolAddress((void**)&Wkt, g_Wkt);
    cudaGetSymbolAddress((void**)&Wvt, g_Wvt);
    cudaGetSymbolAddress((void**)&Wot, g_Wot);
    cudaGetSymbolAddress((void**)&S1, g_S1);
    cudaGetSymbolAddress((void**)&S2, g_S2);
    cudaGetSymbolAddress((void**)&Mb, g_Mb);

    cudaFuncSetAttribute((gemm_l<128, 256, 2, 4, 0, 4>), cudaFuncAttributeMaxDynamicSharedMemorySize, SMEM_BIG);
    cudaFuncSetAttribute((gemm_l<128, 256, 2, 4, 1, 4>), cudaFuncAttributeMaxDynamicSharedMemorySize, SMEM_BIG);
    cudaFuncSetAttribute((gemm_l<128, 256, 2, 4, 2, 4>), cudaFuncAttributeMaxDynamicSharedMemorySize, SMEM_BIG);
    cudaFuncSetAttribute((gemm_l<128, 256, 2, 4, 3, 4>), cudaFuncAttributeMaxDynamicSharedMemorySize, SMEM_BIG);
    cudaFuncSetAttribute((gemm_l<128, 256, 2, 4, 4, 4>), cudaFuncAttributeMaxDynamicSharedMemorySize, SMEM_BIG);
    cudaFuncSetAttribute((gemm_l<128, 64, 4, 2, 0, 4>),  cudaFuncAttributeMaxDynamicSharedMemorySize, SMEM_AV);

    dim3 blk(256);

    // 0: conversions + mask bitpack
    {
        const long nIn = (long)B_ * S_ * D_;          // 4M
        cvt_k<<<(int)(nIn / 1024), blk>>>((const float4*)inq,  (uint2*)Xq);
        cvt_k<<<(int)(nIn / 1024), blk>>>((const float4*)ink,  (uint2*)Xk);
        cvt_k<<<(int)(nIn / 1024), blk>>>((const float4*)invv, (uint2*)Xv);
        cvt_k<<<(int)(((long)S_ * S_) / 1024), blk>>>((const float4*)prop, (uint2*)Ph);
        pack_k<<<(int)(((long)B_ * S_ * S_) / 256), blk>>>(mask, Mb);
        dim3 tg(32, 8), tgr(D_ / 32, D_ / 32);
        tr_k<<<tgr, tg>>>(Wq, Wqt);
        tr_k<<<tgr, tg>>>(Wk, Wkt);
        tr_k<<<tgr, tg>>>(Wv, Wvt);
        tr_k<<<tgr, tg>>>(Wo, Wot);
    }

    // 1-3: projections (NT, K=1024)
    {
        HP p{};
        p.lda = D_; p.ldb = D_; p.ldc = D_;
        p.K = D_;
        dim3 grid(D_ / 256, (B_ * S_) / 128, 1);
        p.A = Xq; p.Bm = Wqt; p.bias = bq; p.C = Qh;
        gemm_l<128, 256, 2, 4, 1, 4><<<grid, blk, SMEM_BIG>>>(p);
        p.A = Xk; p.Bm = Wkt; p.bias = bk; p.C = Kh;
        gemm_l<128, 256, 2, 4, 1, 4><<<grid, blk, SMEM_BIG>>>(p);
        p.A = Xv; p.Bm = Wvt; p.bias = bv; p.C = Vt;   // transposed V store
        gemm_l<128, 256, 2, 4, 3, 4><<<grid, blk, SMEM_BIG>>>(p);
    }

    // 4: S1 = maskbit ? (Q.K^T)/8 : 0   (batched NT, K=64)
    {
        HP p{};
        p.A = Qh; p.lda = D_; p.Ab = (long)S_ * D_; p.Ah = DK_;
        p.Bm = Kh; p.ldb = D_; p.Bb = (long)S_ * D_; p.Bh = DK_;
        p.C = S1; p.ldc = S_; p.Cb = (long)H_ * S_ * S_; p.Ch = (long)S_ * S_;
        p.mask = Mb; p.maskB = (long)S_ * S_ / 32;
        p.scale = 0.125f;
        p.K = DK_;
        dim3 grid(S_ / 256, S_ / 128, B_ * H_);
        gemm_l<128, 256, 2, 4, 2, 4><<<grid, blk, SMEM_BIG>>>(p);
    }

    // 5: S2 = S1 @ P^T   (batched NT, K=2048 — dominant GEMM)
    {
        HP p{};
        p.A = S1; p.lda = S_; p.Ab = (long)H_ * S_ * S_; p.Ah = (long)S_ * S_;
        p.Bm = Ph; p.ldb = S_;
        p.C = S2; p.ldc = S_; p.Cb = (long)H_ * S_ * S_; p.Ch = (long)S_ * S_;
        p.K = S_;
        dim3 grid(S_ / 256, S_ / 128, B_ * H_);
        gemm_l<128, 256, 2, 4, 0, 4><<<grid, blk, SMEM_BIG>>>(p);
    }

    // 6: masked softmax + nan_to_num (in place, fp16, bit mask)
    softmax_h<<<B_ * H_ * S_, 256>>>(S2, Mb);

    // 7: Oh = probs @ V   (batched NT vs Vt, N=64, K=2048)
    {
        HP p{};
        p.A = S2; p.lda = S_; p.Ab = (long)H_ * S_ * S_; p.Ah = (long)S_ * S_;
        p.Bm = Vt; p.ldb = S_; p.Bb = (long)H_ * DK_ * S_; p.Bh = (long)DK_ * S_;
        p.C = Oh; p.ldc = D_; p.Cb = (long)S_ * D_; p.Ch = DK_;
        p.K = S_;
        dim3 grid(1, S_ / 128, B_ * H_);
        gemm_l<128, 64, 4, 2, 0, 4><<<grid, blk, SMEM_AV>>>(p);
    }

    // 8: out = Oh @ Wo + bo   (NT, fp32 store)
    {
        HP p{};
        p.A = Oh; p.lda = D_;
        p.Bm = Wot; p.ldb = D_;
        p.bias = bo;
        p.C = d_out; p.ldc = D_;
        p.K = D_;
        dim3 grid(D_ / 256, (B_ * S_) / 128, 1);
        gemm_l<128, 256, 2, 4, 4, 4><<<grid, blk, SMEM_BIG>>>(p);
    }
}